// round 2
// baseline (speedup 1.0000x reference)
#include <cuda_runtime.h>
#include <cuda_bf16.h>
#include <cstdint>

// Problem dims (fixed by the benchmark)
#define B_DIM 64
#define S_DIM 2048
#define H_DIM 512
#define M_DIM (B_DIM * S_DIM)   // 131072
#define NEG_INF_SCORE (-1e9f)

// GEMM tiling
#define BM 64
#define BN 64
#define BK 16
#define NTILES (H_DIM / BN)      // 8

// Context s-chunking
#define SCHUNK 8
#define S_PER_CHUNK (S_DIM / SCHUNK)  // 256

// Deterministic scratch (no runtime allocation allowed)
__device__ float g_score_part[NTILES * M_DIM];            // 8 * 131072 floats = 4 MB
__device__ float g_ctx_part[SCHUNK * B_DIM * H_DIM];      // 8 * 64 * 512   = 1 MB

// ---------------------------------------------------------------------------
// Kernel 1: fused scores GEMM.
//   part[n_tile][m] = sum over k in n-tile of v[k] * tanh( X[m,:] . W[k,:] + b[k] )
// X row-major [M, H], W row-major [H(k), H(h)] — both K(h)-major, a TN GEMM.
// ---------------------------------------------------------------------------
__global__ void __launch_bounds__(256)
scores_gemm_kernel(const float* __restrict__ X,
                   const float* __restrict__ W,
                   const float* __restrict__ bias,
                   const float* __restrict__ v)
{
    __shared__ float Xs[BM][BK + 1];
    __shared__ float Ws[BN][BK + 1];

    const int m0  = blockIdx.x * BM;
    const int n0  = blockIdx.y * BN;
    const int tid = threadIdx.x;
    const int tx  = tid & 15;    // column-group (n direction), 0..15
    const int ty  = tid >> 4;    // row-group (m direction),    0..15

    // cooperative load mapping: each thread loads one float4 per tile
    const int lr = tid >> 2;           // 0..63
    const int lc = (tid & 3) * 4;      // 0,4,8,12

    const float* Xg = X + (size_t)(m0 + lr) * H_DIM + lc;
    const float* Wg = W + (size_t)(n0 + lr) * H_DIM + lc;

    float acc[4][4] = {};

    for (int k0 = 0; k0 < H_DIM; k0 += BK) {
        float4 xa = *(const float4*)(Xg + k0);
        float4 wa = *(const float4*)(Wg + k0);
        Xs[lr][lc + 0] = xa.x; Xs[lr][lc + 1] = xa.y;
        Xs[lr][lc + 2] = xa.z; Xs[lr][lc + 3] = xa.w;
        Ws[lr][lc + 0] = wa.x; Ws[lr][lc + 1] = wa.y;
        Ws[lr][lc + 2] = wa.z; Ws[lr][lc + 3] = wa.w;
        __syncthreads();

        #pragma unroll
        for (int kk = 0; kk < BK; kk++) {
            float a[4], b[4];
            #pragma unroll
            for (int i = 0; i < 4; i++) a[i] = Xs[ty * 4 + i][kk];
            #pragma unroll
            for (int j = 0; j < 4; j++) b[j] = Ws[tx * 4 + j][kk];
            #pragma unroll
            for (int i = 0; i < 4; i++)
                #pragma unroll
                for (int j = 0; j < 4; j++)
                    acc[i][j] = fmaf(a[i], b[j], acc[i][j]);
        }
        __syncthreads();
    }

    // Epilogue: tanh, scale by v, reduce across the 64 k-columns of this tile.
    float rsum[4] = {0.f, 0.f, 0.f, 0.f};
    #pragma unroll
    for (int j = 0; j < 4; j++) {
        const int cg = n0 + tx * 4 + j;
        const float bv = bias[cg];
        const float vv = v[cg];
        #pragma unroll
        for (int i = 0; i < 4; i++) {
            float x = acc[i][j] + bv;
            float t;
            asm("tanh.approx.f32 %0, %1;" : "=f"(t) : "f"(x));
            rsum[i] += t * vv;
        }
    }

    // Reduce across the 16 threads (tx) that share the same 4 rows.
    #pragma unroll
    for (int off = 8; off > 0; off >>= 1)
        #pragma unroll
        for (int i = 0; i < 4; i++)
            rsum[i] += __shfl_down_sync(0xffffffffu, rsum[i], off, 16);

    if (tx == 0) {
        float* part = g_score_part + (size_t)blockIdx.y * M_DIM;
        #pragma unroll
        for (int i = 0; i < 4; i++)
            part[m0 + ty * 4 + i] = rsum[i];
    }
}

// ---------------------------------------------------------------------------
// Kernel 2: per-batch masked softmax over S. Folds the 8 N-tile partials.
// Mask is read as int32 (JAX bool widened by the harness; nonzero == true).
// ---------------------------------------------------------------------------
__device__ __forceinline__ float warp_max(float v) {
    #pragma unroll
    for (int o = 16; o > 0; o >>= 1) v = fmaxf(v, __shfl_xor_sync(0xffffffffu, v, o));
    return v;
}
__device__ __forceinline__ float warp_sum(float v) {
    #pragma unroll
    for (int o = 16; o > 0; o >>= 1) v += __shfl_xor_sync(0xffffffffu, v, o);
    return v;
}

__global__ void __launch_bounds__(256)
softmax_kernel(const int* __restrict__ mask,
               float* __restrict__ weights)
{
    const int b    = blockIdx.x;
    const int tid  = threadIdx.x;
    const int lane = tid & 31;
    const int wid  = tid >> 5;

    __shared__ float red[8];

    float vals[8];
    float mx = -3.4e38f;
    #pragma unroll
    for (int i = 0; i < 8; i++) {
        const int s = tid + i * 256;
        const size_t m = (size_t)b * S_DIM + s;
        float sc = 0.f;
        #pragma unroll
        for (int n = 0; n < NTILES; n++)
            sc += g_score_part[(size_t)n * M_DIM + m];
        if (mask[m] == 0) sc = NEG_INF_SCORE;
        vals[i] = sc;
        mx = fmaxf(mx, sc);
    }

    mx = warp_max(mx);
    if (lane == 0) red[wid] = mx;
    __syncthreads();
    float bmax = red[0];
    #pragma unroll
    for (int i = 1; i < 8; i++) bmax = fmaxf(bmax, red[i]);
    __syncthreads();

    float s_sum = 0.f;
    #pragma unroll
    for (int i = 0; i < 8; i++) {
        vals[i] = __expf(vals[i] - bmax);
        s_sum += vals[i];
    }
    s_sum = warp_sum(s_sum);
    if (lane == 0) red[wid] = s_sum;
    __syncthreads();
    float total = red[0];
    #pragma unroll
    for (int i = 1; i < 8; i++) total += red[i];

    const float inv = 1.0f / total;
    #pragma unroll
    for (int i = 0; i < 8; i++)
        weights[(size_t)b * S_DIM + tid + i * 256] = vals[i] * inv;
}

// ---------------------------------------------------------------------------
// Kernel 3: context partials. grid (SCHUNK, B), 128 threads, float4 per thread
// covers the full H=512. Memory-bound second pass over hidden.
// ---------------------------------------------------------------------------
__global__ void __launch_bounds__(128)
context_part_kernel(const float* __restrict__ hidden,
                    const float* __restrict__ weights)
{
    const int sc = blockIdx.x;          // 0..7
    const int b  = blockIdx.y;          // 0..63
    const int h4 = threadIdx.x * 4;     // 0..508

    const int s0 = sc * S_PER_CHUNK;
    const float* wrow  = weights + (size_t)b * S_DIM + s0;
    const float* hbase = hidden + ((size_t)b * S_DIM + s0) * H_DIM + h4;

    float4 acc = make_float4(0.f, 0.f, 0.f, 0.f);
    #pragma unroll 4
    for (int s = 0; s < S_PER_CHUNK; s++) {
        const float w = wrow[s];
        float4 hv = *(const float4*)(hbase + (size_t)s * H_DIM);
        acc.x = fmaf(w, hv.x, acc.x);
        acc.y = fmaf(w, hv.y, acc.y);
        acc.z = fmaf(w, hv.z, acc.z);
        acc.w = fmaf(w, hv.w, acc.w);
    }
    *(float4*)(g_ctx_part + ((size_t)(sc * B_DIM + b)) * H_DIM + h4) = acc;
}

// ---------------------------------------------------------------------------
// Kernel 4: reduce the SCHUNK context partials into d_out's context region.
// ---------------------------------------------------------------------------
__global__ void __launch_bounds__(256)
context_reduce_kernel(float* __restrict__ context)
{
    const int i = blockIdx.x * blockDim.x + threadIdx.x;  // 0 .. B*H-1
    float s = 0.f;
    #pragma unroll
    for (int n = 0; n < SCHUNK; n++)
        s += g_ctx_part[(size_t)n * (B_DIM * H_DIM) + i];
    context[i] = s;
}

// ---------------------------------------------------------------------------
extern "C" void kernel_launch(void* const* d_in, const int* in_sizes, int n_in,
                              void* d_out, int out_size)
{
    (void)in_sizes; (void)n_in; (void)out_size;
    const float* hidden = (const float*)d_in[0];
    const int*   mask   = (const int*)d_in[1];
    const float* W      = (const float*)d_in[2];
    const float* bias   = (const float*)d_in[3];
    const float* v      = (const float*)d_in[4];

    float* context = (float*)d_out;                         // [B, H]
    float* weights = (float*)d_out + (size_t)B_DIM * H_DIM; // [B, S]

    dim3 ggrid(M_DIM / BM, NTILES);      // (2048, 8)
    scores_gemm_kernel<<<ggrid, 256>>>(hidden, W, bias, v);

    softmax_kernel<<<B_DIM, 256>>>(mask, weights);

    dim3 cgrid(SCHUNK, B_DIM);           // (8, 64)
    context_part_kernel<<<cgrid, 128>>>(hidden, weights);

    context_reduce_kernel<<<(B_DIM * H_DIM) / 256, 256>>>(context);
}

// round 5
// speedup vs baseline: 2.4904x; 2.4904x over previous
#include <cuda_runtime.h>
#include <cuda_bf16.h>
#include <cstdint>

// ---------------------------------------------------------------------------
// Problem dims
// ---------------------------------------------------------------------------
#define B_DIM 64
#define S_DIM 2048
#define H_DIM 512
#define M_DIM (B_DIM * S_DIM)   // 131072
#define NEG_INF_SCORE (-1e9f)

// GEMM tiling: CTA 128x128, K chunks of 64, 8 warps (4m x 2n), warp 32x64
#define KC 64
#define NKCH (H_DIM / KC)        // 8
#define MT 128
#define NT 128
#define NTILES (H_DIM / NT)      // 4
#define NMTILES (M_DIM / MT)     // 1024

// SMEM stage layout (bytes)
#define A_HI 0
#define A_LO 16384
#define B_HI 32768
#define B_LO 49152
#define STAGE 65536
#define GEMM_SMEM (2 * STAGE)    // 128 KB

// Context s-chunking
#define SCHUNK 8
#define S_PER_CHUNK (S_DIM / SCHUNK)

// ---------------------------------------------------------------------------
// Device scratch (static only). W bf16 hi/lo pre-swizzled tiles: tile (nt,c)
// is 128 n-rows x 64 k, 16 KB, SW128-swizzled 128B rows.
// ---------------------------------------------------------------------------
__device__ __align__(16) __nv_bfloat16 g_Whi[H_DIM * H_DIM];
__device__ __align__(16) __nv_bfloat16 g_Wlo[H_DIM * H_DIM];
__device__ float g_score_part[NTILES * M_DIM];
__device__ float g_ctx_part[SCHUNK * B_DIM * H_DIM];

__device__ __forceinline__ uint32_t smem_u32(const void* p) {
    uint32_t a;
    asm("{ .reg .u64 t; cvta.to.shared.u64 t, %1; cvt.u32.u64 %0, t; }" : "=r"(a) : "l"(p));
    return a;
}
// SW128 swizzle of (row-byte-base, column-byte-offset<128). Exact and in-bounds.
__device__ __forceinline__ uint32_t swz(uint32_t rowoff, uint32_t col) {
    return rowoff + (col ^ ((rowoff >> 3) & 0x70));
}

__device__ __forceinline__ void cp_async16(uint32_t dst, const void* src) {
    asm volatile("cp.async.cg.shared.global [%0], [%1], 16;"
                 :: "r"(dst), "l"(__cvta_generic_to_global(src)) : "memory");
}
__device__ __forceinline__ void cp_async_commit() {
    asm volatile("cp.async.commit_group;" ::: "memory");
}
__device__ __forceinline__ void cp_async_wait0() {
    asm volatile("cp.async.wait_group 0;" ::: "memory");
}

__device__ __forceinline__ void ldsm_x4(uint32_t* r, uint32_t addr) {
    asm volatile("ldmatrix.sync.aligned.m8n8.x4.shared.b16 {%0,%1,%2,%3}, [%4];"
                 : "=r"(r[0]), "=r"(r[1]), "=r"(r[2]), "=r"(r[3]) : "r"(addr));
}

__device__ __forceinline__ void mma16816(float* d, const uint32_t* a, uint32_t b0, uint32_t b1) {
    asm volatile(
        "mma.sync.aligned.m16n8k16.row.col.f32.bf16.bf16.f32 "
        "{%0,%1,%2,%3}, {%4,%5,%6,%7}, {%8,%9}, {%0,%1,%2,%3};"
        : "+f"(d[0]), "+f"(d[1]), "+f"(d[2]), "+f"(d[3])
        : "r"(a[0]), "r"(a[1]), "r"(a[2]), "r"(a[3]), "r"(b0), "r"(b1));
}

// pack 4 floats -> hi uint2 + lo uint2 (bf16 pairs)
__device__ __forceinline__ void split4(float4 xv, uint2* hi, uint2* lo) {
    __nv_bfloat16 h0 = __float2bfloat16(xv.x);
    __nv_bfloat16 h1 = __float2bfloat16(xv.y);
    __nv_bfloat16 h2 = __float2bfloat16(xv.z);
    __nv_bfloat16 h3 = __float2bfloat16(xv.w);
    __nv_bfloat16 l0 = __float2bfloat16(xv.x - __bfloat162float(h0));
    __nv_bfloat16 l1 = __float2bfloat16(xv.y - __bfloat162float(h1));
    __nv_bfloat16 l2 = __float2bfloat16(xv.z - __bfloat162float(h2));
    __nv_bfloat16 l3 = __float2bfloat16(xv.w - __bfloat162float(h3));
    union { __nv_bfloat162 b2[2]; uint2 u; } ph, pl;
    ph.b2[0] = __halves2bfloat162(h0, h1); ph.b2[1] = __halves2bfloat162(h2, h3);
    pl.b2[0] = __halves2bfloat162(l0, l1); pl.b2[1] = __halves2bfloat162(l2, l3);
    *hi = ph.u; *lo = pl.u;
}

// ---------------------------------------------------------------------------
// W pre-convert: fp32 [512(n),512(k)] -> pre-swizzled bf16 hi/lo tiles
// grid: 32 blocks (nt*8+c), 256 threads
// ---------------------------------------------------------------------------
__global__ void __launch_bounds__(256)
convert_w_kernel(const float* __restrict__ W)
{
    const int nt = blockIdx.x >> 3;
    const int c  = blockIdx.x & 7;
    const int tid = threadIdx.x;
    const int row = tid >> 1;              // 0..127 (n within tile)
    const int kh  = (tid & 1) * 32;        // k element offset half-row

    const float* src = W + (size_t)(nt * NT + row) * H_DIM + c * KC + kh;
    char* dhi = (char*)g_Whi + (size_t)(blockIdx.x) * 16384;
    char* dlo = (char*)g_Wlo + (size_t)(blockIdx.x) * 16384;

    const uint32_t rowoff = (uint32_t)row * 128;
    #pragma unroll
    for (int i = 0; i < 8; i++) {
        float4 xv = *(const float4*)(src + i * 4);
        uint2 hi, lo;
        split4(xv, &hi, &lo);
        const uint32_t off = swz(rowoff, (uint32_t)(kh * 2 + i * 8));
        *(uint2*)(dhi + off) = hi;
        *(uint2*)(dlo + off) = lo;
    }
}

// ---------------------------------------------------------------------------
// Scores GEMM via mma.sync (bf16 hi/lo split, fp32 accum), fused tanh.v reduce
// grid (1024 m-tiles, 4 n-tiles), 256 threads
// ---------------------------------------------------------------------------
__global__ void __launch_bounds__(256)
scores_gemm_mma(const float* __restrict__ X,
                const float* __restrict__ bias,
                const float* __restrict__ v)
{
    extern __shared__ char smem[];
    __shared__ float red[MT];

    const uint32_t sb = smem_u32(smem);
    const int tid  = threadIdx.x;
    const int wid  = tid >> 5;
    const int lane = tid & 31;
    const int wm   = wid & 3;      // warp m index (0..3)
    const int wn   = wid >> 2;     // warp n index (0..1)
    const int t  = blockIdx.x;     // m-tile
    const int nt = blockIdx.y;     // n-tile

    // A global mapping: each thread owns half a row (32 k-elems) per chunk
    const int arow = tid >> 1;               // 0..127
    const int akh  = (tid & 1) * 32;         // k element offset
    const float* aptr = X + (size_t)(t * MT + arow) * H_DIM + akh;
    const uint32_t a_rowoff = (uint32_t)arow * 128;
    const uint32_t a_colbase = (uint32_t)(akh * 2);   // 0 or 64 bytes

    // B global tiles (pre-swizzled 16KB blobs)
    const char* bhig = (const char*)g_Whi + (size_t)(nt * NKCH) * 16384;
    const char* blog = (const char*)g_Wlo + (size_t)(nt * NKCH) * 16384;

    // ldmatrix row bases; column = kb + ks*32 composed inside the swizzle
    const int lrow = lane & 15;
    const uint32_t kb = (lane >> 4) * 16;
    uint32_t a_rowb[2], b_rowb[4];
    #pragma unroll
    for (int mi = 0; mi < 2; mi++)
        a_rowb[mi] = (uint32_t)(wm * 32 + mi * 16 + lrow) * 128;
    #pragma unroll
    for (int np = 0; np < 4; np++)
        b_rowb[np] = (uint32_t)(wn * 64 + np * 16 + lrow) * 128;

    float acc[2][8][4];
    #pragma unroll
    for (int mi = 0; mi < 2; mi++)
        #pragma unroll
        for (int ni = 0; ni < 8; ni++)
            #pragma unroll
            for (int j = 0; j < 4; j++) acc[mi][ni][j] = 0.f;

    // ---- prologue: chunk 0 ----
    {
        float4 areg[8];
        #pragma unroll
        for (int i = 0; i < 8; i++) areg[i] = *(const float4*)(aptr + i * 4);
        #pragma unroll
        for (int i = 0; i < 8; i++) {
            uint2 hi, lo;
            split4(areg[i], &hi, &lo);
            const uint32_t off = swz(a_rowoff, a_colbase + i * 8);
            *(uint2*)(smem + A_HI + off) = hi;
            *(uint2*)(smem + A_LO + off) = lo;
        }
        #pragma unroll
        for (int it = 0; it < 4; it++) {
            cp_async16(sb + B_HI + tid * 16 + it * 4096, bhig + tid * 16 + it * 4096);
            cp_async16(sb + B_LO + tid * 16 + it * 4096, blog + tid * 16 + it * 4096);
        }
        cp_async_commit();
    }

    for (int c = 0; c < NKCH; c++) {
        cp_async_wait0();
        __syncthreads();

        const int cur = c & 1;
        const int nxt = cur ^ 1;
        float4 areg[8];
        if (c + 1 < NKCH) {
            #pragma unroll
            for (int i = 0; i < 8; i++)
                areg[i] = *(const float4*)(aptr + (c + 1) * KC + i * 4);
            const char* bh = bhig + (size_t)(c + 1) * 16384;
            const char* bl = blog + (size_t)(c + 1) * 16384;
            #pragma unroll
            for (int it = 0; it < 4; it++) {
                cp_async16(sb + nxt * STAGE + B_HI + tid * 16 + it * 4096, bh + tid * 16 + it * 4096);
                cp_async16(sb + nxt * STAGE + B_LO + tid * 16 + it * 4096, bl + tid * 16 + it * 4096);
            }
            cp_async_commit();
        }

        // ---- compute chunk c ----
        const uint32_t st = sb + cur * STAGE;
        #pragma unroll
        for (int ks = 0; ks < KC / 16; ks++) {
            const uint32_t kcol = kb + ks * 32;    // < 128, composed into swizzle
            uint32_t ahi[2][4], alo[2][4], bhi[4][4], blo[4][4];
            #pragma unroll
            for (int mi = 0; mi < 2; mi++) {
                const uint32_t ao = swz(a_rowb[mi], kcol);
                ldsm_x4(ahi[mi], st + A_HI + ao);
                ldsm_x4(alo[mi], st + A_LO + ao);
            }
            #pragma unroll
            for (int np = 0; np < 4; np++) {
                const uint32_t bo = swz(b_rowb[np], kcol);
                ldsm_x4(bhi[np], st + B_HI + bo);
                ldsm_x4(blo[np], st + B_LO + bo);
            }
            #pragma unroll
            for (int mi = 0; mi < 2; mi++)
                #pragma unroll
                for (int np = 0; np < 4; np++)
                    #pragma unroll
                    for (int hf = 0; hf < 2; hf++) {
                        float* d = acc[mi][np * 2 + hf];
                        mma16816(d, ahi[mi], bhi[np][hf], bhi[np][hf + 2]);
                        mma16816(d, ahi[mi], blo[np][hf], blo[np][hf + 2]);
                        mma16816(d, alo[mi], bhi[np][hf], bhi[np][hf + 2]);
                    }
        }

        if (c + 1 < NKCH) {
            #pragma unroll
            for (int i = 0; i < 8; i++) {
                uint2 hi, lo;
                split4(areg[i], &hi, &lo);
                const uint32_t off = swz(a_rowoff, a_colbase + i * 8);
                *(uint2*)(smem + nxt * STAGE + A_HI + off) = hi;
                *(uint2*)(smem + nxt * STAGE + A_LO + off) = lo;
            }
        }
    }

    // ---- epilogue: rsum[row] = sum_n v[n]*tanh(acc + b[n]) ----
    const int ncol0 = nt * NT + wn * 64 + (lane & 3) * 2;
    float rs[2][2] = {{0.f, 0.f}, {0.f, 0.f}};
    #pragma unroll
    for (int ni = 0; ni < 8; ni++) {
        #pragma unroll
        for (int cc = 0; cc < 2; cc++) {
            const int col = ncol0 + ni * 8 + cc;
            const float bb = bias[col];
            const float vv = v[col];
            #pragma unroll
            for (int mi = 0; mi < 2; mi++) {
                float x0 = acc[mi][ni][cc] + bb;        // row groupID
                float x1 = acc[mi][ni][cc + 2] + bb;    // row groupID+8
                float t0, t1;
                asm("tanh.approx.f32 %0, %1;" : "=f"(t0) : "f"(x0));
                asm("tanh.approx.f32 %0, %1;" : "=f"(t1) : "f"(x1));
                rs[mi][0] = fmaf(t0, vv, rs[mi][0]);
                rs[mi][1] = fmaf(t1, vv, rs[mi][1]);
            }
        }
    }
    // reduce across the 4 lanes sharing a row (lane bits 0-1)
    #pragma unroll
    for (int mi = 0; mi < 2; mi++)
        #pragma unroll
        for (int h = 0; h < 2; h++) {
            rs[mi][h] += __shfl_xor_sync(0xffffffffu, rs[mi][h], 1);
            rs[mi][h] += __shfl_xor_sync(0xffffffffu, rs[mi][h], 2);
        }

    __syncthreads();   // all compute done before red[] reuse
    if (wn == 1 && (lane & 3) == 0) {
        #pragma unroll
        for (int mi = 0; mi < 2; mi++)
            #pragma unroll
            for (int h = 0; h < 2; h++)
                red[wm * 32 + mi * 16 + h * 8 + (lane >> 2)] = rs[mi][h];
    }
    __syncthreads();
    if (wn == 0 && (lane & 3) == 0) {
        #pragma unroll
        for (int mi = 0; mi < 2; mi++)
            #pragma unroll
            for (int h = 0; h < 2; h++) {
                const int row = wm * 32 + mi * 16 + h * 8 + (lane >> 2);
                g_score_part[(size_t)nt * M_DIM + (size_t)t * MT + row] =
                    rs[mi][h] + red[row];
            }
    }
}

// ---------------------------------------------------------------------------
// Softmax (folds 4 n-tile partials), mask as int32
// ---------------------------------------------------------------------------
__device__ __forceinline__ float warp_max(float v) {
    #pragma unroll
    for (int o = 16; o > 0; o >>= 1) v = fmaxf(v, __shfl_xor_sync(0xffffffffu, v, o));
    return v;
}
__device__ __forceinline__ float warp_sum(float v) {
    #pragma unroll
    for (int o = 16; o > 0; o >>= 1) v += __shfl_xor_sync(0xffffffffu, v, o);
    return v;
}

__global__ void __launch_bounds__(256)
softmax_kernel(const int* __restrict__ mask, float* __restrict__ weights)
{
    const int b    = blockIdx.x;
    const int tid  = threadIdx.x;
    const int lane = tid & 31;
    const int wid  = tid >> 5;

    __shared__ float red[8];

    float vals[8];
    float mx = -3.4e38f;
    #pragma unroll
    for (int i = 0; i < 8; i++) {
        const size_t m = (size_t)b * S_DIM + tid + i * 256;
        float sc = 0.f;
        #pragma unroll
        for (int n = 0; n < NTILES; n++)
            sc += g_score_part[(size_t)n * M_DIM + m];
        if (mask[m] == 0) sc = NEG_INF_SCORE;
        vals[i] = sc;
        mx = fmaxf(mx, sc);
    }

    mx = warp_max(mx);
    if (lane == 0) red[wid] = mx;
    __syncthreads();
    float bmax = red[0];
    #pragma unroll
    for (int i = 1; i < 8; i++) bmax = fmaxf(bmax, red[i]);
    __syncthreads();

    float s_sum = 0.f;
    #pragma unroll
    for (int i = 0; i < 8; i++) {
        vals[i] = __expf(vals[i] - bmax);
        s_sum += vals[i];
    }
    s_sum = warp_sum(s_sum);
    if (lane == 0) red[wid] = s_sum;
    __syncthreads();
    float total = red[0];
    #pragma unroll
    for (int i = 1; i < 8; i++) total += red[i];

    const float inv = 1.0f / total;
    #pragma unroll
    for (int i = 0; i < 8; i++)
        weights[(size_t)b * S_DIM + tid + i * 256] = vals[i] * inv;
}

// ---------------------------------------------------------------------------
// Context: weighted sum over S (memory-bound second pass over hidden)
// ---------------------------------------------------------------------------
__global__ void __launch_bounds__(128)
context_part_kernel(const float* __restrict__ hidden, const float* __restrict__ weights)
{
    const int sc = blockIdx.x;
    const int b  = blockIdx.y;
    const int h4 = threadIdx.x * 4;

    const int s0 = sc * S_PER_CHUNK;
    const float* wrow  = weights + (size_t)b * S_DIM + s0;
    const float* hbase = hidden + ((size_t)b * S_DIM + s0) * H_DIM + h4;

    float4 acc = make_float4(0.f, 0.f, 0.f, 0.f);
    #pragma unroll 4
    for (int s = 0; s < S_PER_CHUNK; s++) {
        const float w = wrow[s];
        float4 hv = *(const float4*)(hbase + (size_t)s * H_DIM);
        acc.x = fmaf(w, hv.x, acc.x);
        acc.y = fmaf(w, hv.y, acc.y);
        acc.z = fmaf(w, hv.z, acc.z);
        acc.w = fmaf(w, hv.w, acc.w);
    }
    *(float4*)(g_ctx_part + ((size_t)(sc * B_DIM + b)) * H_DIM + h4) = acc;
}

__global__ void __launch_bounds__(256)
context_reduce_kernel(float* __restrict__ context)
{
    const int i = blockIdx.x * blockDim.x + threadIdx.x;
    float s = 0.f;
    #pragma unroll
    for (int n = 0; n < SCHUNK; n++)
        s += g_ctx_part[(size_t)n * (B_DIM * H_DIM) + i];
    context[i] = s;
}

// ---------------------------------------------------------------------------
extern "C" void kernel_launch(void* const* d_in, const int* in_sizes, int n_in,
                              void* d_out, int out_size)
{
    (void)in_sizes; (void)n_in; (void)out_size;
    const float* hidden = (const float*)d_in[0];
    const int*   mask   = (const int*)d_in[1];
    const float* W      = (const float*)d_in[2];
    const float* bias   = (const float*)d_in[3];
    const float* v      = (const float*)d_in[4];

    float* context = (float*)d_out;                          // [B, H]
    float* weights = (float*)d_out + (size_t)B_DIM * H_DIM;  // [B, S]

    cudaFuncSetAttribute(scores_gemm_mma,
                         cudaFuncAttributeMaxDynamicSharedMemorySize, GEMM_SMEM);

    convert_w_kernel<<<NTILES * NKCH, 256>>>(W);

    scores_gemm_mma<<<dim3(NMTILES, NTILES), 256, GEMM_SMEM>>>(hidden, bias, v);

    softmax_kernel<<<B_DIM, 256>>>(mask, weights);

    context_part_kernel<<<dim3(SCHUNK, B_DIM), 128>>>(hidden, weights);
    context_reduce_kernel<<<(B_DIM * H_DIM) / 256, 256>>>(context);
}

// round 6
// speedup vs baseline: 2.9658x; 1.1909x over previous
#include <cuda_runtime.h>
#include <cuda_bf16.h>
#include <cstdint>

// ---------------------------------------------------------------------------
// Problem dims
// ---------------------------------------------------------------------------
#define B_DIM 64
#define S_DIM 2048
#define H_DIM 512
#define M_DIM (B_DIM * S_DIM)   // 131072
#define NEG_INF_SCORE (-1e9f)

// GEMM tiling: CTA 128x128, K chunks of 64, 16 warps (4m x 4n), warp 32x32
#define KC 64
#define NKCH (H_DIM / KC)        // 8
#define MT 128
#define NT 128
#define NTILES (H_DIM / NT)      // 4
#define NMTILES (M_DIM / MT)     // 1024
#define NSTAGE 3

// SMEM stage layout (bytes)
#define A_HI 0
#define A_LO 16384
#define B_HI 32768
#define B_LO 49152
#define STAGE 65536
#define GEMM_SMEM (NSTAGE * STAGE)   // 192 KB

// Context s-chunking
#define SCHUNK 32
#define S_PER_CHUNK (S_DIM / SCHUNK)  // 64

// ---------------------------------------------------------------------------
// Device scratch (static only). W bf16 hi/lo pre-swizzled tiles: tile (nt,c)
// is 128 n-rows x 64 k, 16 KB, SW128-swizzled 128B rows.
// ---------------------------------------------------------------------------
__device__ __align__(16) __nv_bfloat16 g_Whi[H_DIM * H_DIM];
__device__ __align__(16) __nv_bfloat16 g_Wlo[H_DIM * H_DIM];
__device__ float g_score_part[NTILES * M_DIM];
__device__ float g_ctx_part[SCHUNK * B_DIM * H_DIM];

__device__ __forceinline__ uint32_t smem_u32(const void* p) {
    uint32_t a;
    asm("{ .reg .u64 t; cvta.to.shared.u64 t, %1; cvt.u32.u64 %0, t; }" : "=r"(a) : "l"(p));
    return a;
}
// SW128 swizzle of (row-byte-base, column-byte-offset<128). Exact and in-bounds.
__device__ __forceinline__ uint32_t swz(uint32_t rowoff, uint32_t col) {
    return rowoff + (col ^ ((rowoff >> 3) & 0x70));
}

__device__ __forceinline__ void cp_async16(uint32_t dst, const void* src) {
    asm volatile("cp.async.cg.shared.global [%0], [%1], 16;"
                 :: "r"(dst), "l"(__cvta_generic_to_global(src)) : "memory");
}
__device__ __forceinline__ void cp_async_commit() {
    asm volatile("cp.async.commit_group;" ::: "memory");
}
__device__ __forceinline__ void cp_async_wait0() {
    asm volatile("cp.async.wait_group 0;" ::: "memory");
}

__device__ __forceinline__ void ldsm_x4(uint32_t* r, uint32_t addr) {
    asm volatile("ldmatrix.sync.aligned.m8n8.x4.shared.b16 {%0,%1,%2,%3}, [%4];"
                 : "=r"(r[0]), "=r"(r[1]), "=r"(r[2]), "=r"(r[3]) : "r"(addr));
}

__device__ __forceinline__ void mma16816(float* d, const uint32_t* a, uint32_t b0, uint32_t b1) {
    asm volatile(
        "mma.sync.aligned.m16n8k16.row.col.f32.bf16.bf16.f32 "
        "{%0,%1,%2,%3}, {%4,%5,%6,%7}, {%8,%9}, {%0,%1,%2,%3};"
        : "+f"(d[0]), "+f"(d[1]), "+f"(d[2]), "+f"(d[3])
        : "r"(a[0]), "r"(a[1]), "r"(a[2]), "r"(a[3]), "r"(b0), "r"(b1));
}

// pack 4 floats -> hi uint2 + lo uint2 (bf16 pairs)
__device__ __forceinline__ void split4(float4 xv, uint2* hi, uint2* lo) {
    __nv_bfloat16 h0 = __float2bfloat16(xv.x);
    __nv_bfloat16 h1 = __float2bfloat16(xv.y);
    __nv_bfloat16 h2 = __float2bfloat16(xv.z);
    __nv_bfloat16 h3 = __float2bfloat16(xv.w);
    __nv_bfloat16 l0 = __float2bfloat16(xv.x - __bfloat162float(h0));
    __nv_bfloat16 l1 = __float2bfloat16(xv.y - __bfloat162float(h1));
    __nv_bfloat16 l2 = __float2bfloat16(xv.z - __bfloat162float(h2));
    __nv_bfloat16 l3 = __float2bfloat16(xv.w - __bfloat162float(h3));
    union { __nv_bfloat162 b2[2]; uint2 u; } ph, pl;
    ph.b2[0] = __halves2bfloat162(h0, h1); ph.b2[1] = __halves2bfloat162(h2, h3);
    pl.b2[0] = __halves2bfloat162(l0, l1); pl.b2[1] = __halves2bfloat162(l2, l3);
    *hi = ph.u; *lo = pl.u;
}

// ---------------------------------------------------------------------------
// W pre-convert: fp32 [512(n),512(k)] -> pre-swizzled bf16 hi/lo tiles
// grid: 32 blocks (nt*8+c), 256 threads
// ---------------------------------------------------------------------------
__global__ void __launch_bounds__(256)
convert_w_kernel(const float* __restrict__ W)
{
    const int nt = blockIdx.x >> 3;
    const int c  = blockIdx.x & 7;
    const int tid = threadIdx.x;
    const int row = tid >> 1;              // 0..127 (n within tile)
    const int kh  = (tid & 1) * 32;        // k element offset half-row

    const float* src = W + (size_t)(nt * NT + row) * H_DIM + c * KC + kh;
    char* dhi = (char*)g_Whi + (size_t)(blockIdx.x) * 16384;
    char* dlo = (char*)g_Wlo + (size_t)(blockIdx.x) * 16384;

    const uint32_t rowoff = (uint32_t)row * 128;
    #pragma unroll
    for (int i = 0; i < 8; i++) {
        float4 xv = *(const float4*)(src + i * 4);
        uint2 hi, lo;
        split4(xv, &hi, &lo);
        const uint32_t off = swz(rowoff, (uint32_t)(kh * 2 + i * 8));
        *(uint2*)(dhi + off) = hi;
        *(uint2*)(dlo + off) = lo;
    }
}

// ---------------------------------------------------------------------------
// Scores GEMM via mma.sync (bf16 hi/lo split, fp32 accum), fused tanh.v reduce
// grid (1024 m-tiles, 4 n-tiles), 512 threads / 16 warps (4m x 4n)
// 3-stage pipeline.
// ---------------------------------------------------------------------------
__global__ void __launch_bounds__(512, 1)
scores_gemm_mma(const float* __restrict__ X,
                const float* __restrict__ bias,
                const float* __restrict__ v)
{
    extern __shared__ char smem[];
    __shared__ float red[4][MT];

    const uint32_t sb = smem_u32(smem);
    const int tid  = threadIdx.x;
    const int wid  = tid >> 5;
    const int lane = tid & 31;
    const int wm   = wid & 3;      // warp m index (0..3)
    const int wn   = wid >> 2;     // warp n index (0..3)
    const int t  = blockIdx.x;     // m-tile
    const int nt = blockIdx.y;     // n-tile

    // A global mapping: thread owns row = tid>>2, k-quarter = (tid&3)*16 elems
    const int arow = tid >> 2;                // 0..127
    const int akq  = (tid & 3) * 16;          // k element offset (16 elems)
    const float* aptr = X + (size_t)(t * MT + arow) * H_DIM + akq;
    const uint32_t a_rowoff = (uint32_t)arow * 128;
    const uint32_t a_colbase = (uint32_t)(akq * 2);   // 0,32,64,96 bytes

    // B global tiles (pre-swizzled 16KB blobs)
    const char* bhig = (const char*)g_Whi + (size_t)(nt * NKCH) * 16384;
    const char* blog = (const char*)g_Wlo + (size_t)(nt * NKCH) * 16384;

    // ldmatrix row bases; column = kb + ks*32 composed inside the swizzle
    const int lrow = lane & 15;
    const uint32_t kb = (lane >> 4) * 16;
    uint32_t a_rowb[2], b_rowb[2];
    #pragma unroll
    for (int mi = 0; mi < 2; mi++)
        a_rowb[mi] = (uint32_t)(wm * 32 + mi * 16 + lrow) * 128;
    #pragma unroll
    for (int np = 0; np < 2; np++)
        b_rowb[np] = (uint32_t)(wn * 32 + np * 16 + lrow) * 128;

    float acc[2][4][4];
    #pragma unroll
    for (int mi = 0; mi < 2; mi++)
        #pragma unroll
        for (int ni = 0; ni < 4; ni++)
            #pragma unroll
            for (int j = 0; j < 4; j++) acc[mi][ni][j] = 0.f;

    // helper lambdas ------------------------------------------------------
    auto b_load = [&](int c) {   // cp.async B hi+lo for chunk c into stage c%3
        const uint32_t stb = sb + (uint32_t)(c % NSTAGE) * STAGE;
        const char* bh = bhig + (size_t)c * 16384;
        const char* bl = blog + (size_t)c * 16384;
        #pragma unroll
        for (int it = 0; it < 2; it++) {
            cp_async16(stb + B_HI + tid * 16 + it * 8192, bh + tid * 16 + it * 8192);
            cp_async16(stb + B_LO + tid * 16 + it * 8192, bl + tid * 16 + it * 8192);
        }
        cp_async_commit();
    };
    auto a_ldg = [&](int c, float4* areg) {
        #pragma unroll
        for (int i = 0; i < 4; i++)
            areg[i] = *(const float4*)(aptr + c * KC + i * 4);
    };
    auto a_sts = [&](int c, const float4* areg) {
        char* st = smem + (size_t)(c % NSTAGE) * STAGE;
        #pragma unroll
        for (int i = 0; i < 4; i++) {
            uint2 hi, lo;
            split4(areg[i], &hi, &lo);
            const uint32_t off = swz(a_rowoff, a_colbase + i * 8);
            *(uint2*)(st + A_HI + off) = hi;
            *(uint2*)(st + A_LO + off) = lo;
        }
    };

    // ---- prologue: chunks 0 and 1 ----
    {
        b_load(0);
        b_load(1);
        float4 ar0[4], ar1[4];
        a_ldg(0, ar0);
        a_ldg(1, ar1);
        a_sts(0, ar0);
        a_sts(1, ar1);
    }
    __syncthreads();

    for (int c = 0; c < NKCH; c++) {
        // B(c) was committed 2 iterations back; one newer group may be pending
        if (c == NKCH - 1) cp_async_wait0();
        else asm volatile("cp.async.wait_group 1;" ::: "memory");
        __syncthreads();

        float4 areg[4];
        if (c + 2 < NKCH) {
            b_load(c + 2);          // async, overlaps compute below
            a_ldg(c + 2, areg);     // latency hidden by compute
        }

        // ---- compute chunk c ----
        const uint32_t st = sb + (uint32_t)(c % NSTAGE) * STAGE;
        #pragma unroll
        for (int ks = 0; ks < KC / 16; ks++) {
            const uint32_t kcol = kb + ks * 32;    // < 128, composed into swizzle
            uint32_t ahi[2][4], alo[2][4], bhi[2][4], blo[2][4];
            #pragma unroll
            for (int mi = 0; mi < 2; mi++) {
                const uint32_t ao = swz(a_rowb[mi], kcol);
                ldsm_x4(ahi[mi], st + A_HI + ao);
                ldsm_x4(alo[mi], st + A_LO + ao);
            }
            #pragma unroll
            for (int np = 0; np < 2; np++) {
                const uint32_t bo = swz(b_rowb[np], kcol);
                ldsm_x4(bhi[np], st + B_HI + bo);
                ldsm_x4(blo[np], st + B_LO + bo);
            }
            #pragma unroll
            for (int mi = 0; mi < 2; mi++)
                #pragma unroll
                for (int np = 0; np < 2; np++)
                    #pragma unroll
                    for (int hf = 0; hf < 2; hf++) {
                        float* d = acc[mi][np * 2 + hf];
                        mma16816(d, ahi[mi], bhi[np][hf], bhi[np][hf + 2]);
                        mma16816(d, ahi[mi], blo[np][hf], blo[np][hf + 2]);
                        mma16816(d, alo[mi], bhi[np][hf], bhi[np][hf + 2]);
                    }
        }

        if (c + 2 < NKCH)
            a_sts(c + 2, areg);     // stage (c+2)%3 is free (consumed at c-1)
    }

    // ---- epilogue: rsum[row] = sum_n v[n]*tanh(acc + b[n]) ----
    const int ncol0 = nt * NT + wn * 32 + (lane & 3) * 2;
    float rs[2][2] = {{0.f, 0.f}, {0.f, 0.f}};
    #pragma unroll
    for (int np = 0; np < 2; np++) {
        #pragma unroll
        for (int hf = 0; hf < 2; hf++) {
            #pragma unroll
            for (int cc = 0; cc < 2; cc++) {
                const int col = ncol0 + np * 16 + hf * 8 + cc;
                const float bb = bias[col];
                const float vv = v[col];
                #pragma unroll
                for (int mi = 0; mi < 2; mi++) {
                    float x0 = acc[mi][np * 2 + hf][cc] + bb;       // row groupID
                    float x1 = acc[mi][np * 2 + hf][cc + 2] + bb;   // row groupID+8
                    float t0, t1;
                    asm("tanh.approx.f32 %0, %1;" : "=f"(t0) : "f"(x0));
                    asm("tanh.approx.f32 %0, %1;" : "=f"(t1) : "f"(x1));
                    rs[mi][0] = fmaf(t0, vv, rs[mi][0]);
                    rs[mi][1] = fmaf(t1, vv, rs[mi][1]);
                }
            }
        }
    }
    // reduce across the 4 lanes sharing a row (lane bits 0-1)
    #pragma unroll
    for (int mi = 0; mi < 2; mi++)
        #pragma unroll
        for (int h = 0; h < 2; h++) {
            rs[mi][h] += __shfl_xor_sync(0xffffffffu, rs[mi][h], 1);
            rs[mi][h] += __shfl_xor_sync(0xffffffffu, rs[mi][h], 2);
        }

    __syncthreads();   // all compute done before red[] use
    if ((lane & 3) == 0) {
        #pragma unroll
        for (int mi = 0; mi < 2; mi++)
            #pragma unroll
            for (int h = 0; h < 2; h++)
                red[wn][wm * 32 + mi * 16 + h * 8 + (lane >> 2)] = rs[mi][h];
    }
    __syncthreads();
    if (tid < MT) {
        float s = red[0][tid] + red[1][tid] + red[2][tid] + red[3][tid];
        g_score_part[(size_t)nt * M_DIM + (size_t)t * MT + tid] = s;
    }
}

// ---------------------------------------------------------------------------
// Softmax (folds 4 n-tile partials), mask as int32
// ---------------------------------------------------------------------------
__device__ __forceinline__ float warp_max(float v) {
    #pragma unroll
    for (int o = 16; o > 0; o >>= 1) v = fmaxf(v, __shfl_xor_sync(0xffffffffu, v, o));
    return v;
}
__device__ __forceinline__ float warp_sum(float v) {
    #pragma unroll
    for (int o = 16; o > 0; o >>= 1) v += __shfl_xor_sync(0xffffffffu, v, o);
    return v;
}

__global__ void __launch_bounds__(256)
softmax_kernel(const int* __restrict__ mask, float* __restrict__ weights)
{
    const int b    = blockIdx.x;
    const int tid  = threadIdx.x;
    const int lane = tid & 31;
    const int wid  = tid >> 5;

    __shared__ float red[8];

    float vals[8];
    float mx = -3.4e38f;
    #pragma unroll
    for (int i = 0; i < 8; i++) {
        const size_t m = (size_t)b * S_DIM + tid + i * 256;
        float sc = 0.f;
        #pragma unroll
        for (int n = 0; n < NTILES; n++)
            sc += g_score_part[(size_t)n * M_DIM + m];
        if (mask[m] == 0) sc = NEG_INF_SCORE;
        vals[i] = sc;
        mx = fmaxf(mx, sc);
    }

    mx = warp_max(mx);
    if (lane == 0) red[wid] = mx;
    __syncthreads();
    float bmax = red[0];
    #pragma unroll
    for (int i = 1; i < 8; i++) bmax = fmaxf(bmax, red[i]);
    __syncthreads();

    float s_sum = 0.f;
    #pragma unroll
    for (int i = 0; i < 8; i++) {
        vals[i] = __expf(vals[i] - bmax);
        s_sum += vals[i];
    }
    s_sum = warp_sum(s_sum);
    if (lane == 0) red[wid] = s_sum;
    __syncthreads();
    float total = red[0];
    #pragma unroll
    for (int i = 1; i < 8; i++) total += red[i];

    const float inv = 1.0f / total;
    #pragma unroll
    for (int i = 0; i < 8; i++)
        weights[(size_t)b * S_DIM + tid + i * 256] = vals[i] * inv;
}

// ---------------------------------------------------------------------------
// Context: weighted sum over S (memory-bound second pass over hidden)
// ---------------------------------------------------------------------------
__global__ void __launch_bounds__(128)
context_part_kernel(const float* __restrict__ hidden, const float* __restrict__ weights)
{
    const int sc = blockIdx.x;          // 0..31
    const int b  = blockIdx.y;          // 0..63
    const int h4 = threadIdx.x * 4;

    const int s0 = sc * S_PER_CHUNK;
    const float* wrow  = weights + (size_t)b * S_DIM + s0;
    const float* hbase = hidden + ((size_t)b * S_DIM + s0) * H_DIM + h4;

    float4 acc = make_float4(0.f, 0.f, 0.f, 0.f);
    #pragma unroll 8
    for (int s = 0; s < S_PER_CHUNK; s++) {
        const float w = wrow[s];
        float4 hv = *(const float4*)(hbase + (size_t)s * H_DIM);
        acc.x = fmaf(w, hv.x, acc.x);
        acc.y = fmaf(w, hv.y, acc.y);
        acc.z = fmaf(w, hv.z, acc.z);
        acc.w = fmaf(w, hv.w, acc.w);
    }
    *(float4*)(g_ctx_part + ((size_t)(sc * B_DIM + b)) * H_DIM + h4) = acc;
}

__global__ void __launch_bounds__(256)
context_reduce_kernel(float* __restrict__ context)
{
    const int i = blockIdx.x * blockDim.x + threadIdx.x;
    float s = 0.f;
    #pragma unroll
    for (int n = 0; n < SCHUNK; n++)
        s += g_ctx_part[(size_t)n * (B_DIM * H_DIM) + i];
    context[i] = s;
}

// ---------------------------------------------------------------------------
extern "C" void kernel_launch(void* const* d_in, const int* in_sizes, int n_in,
                              void* d_out, int out_size)
{
    (void)in_sizes; (void)n_in; (void)out_size;
    const float* hidden = (const float*)d_in[0];
    const int*   mask   = (const int*)d_in[1];
    const float* W      = (const float*)d_in[2];
    const float* bias   = (const float*)d_in[3];
    const float* v      = (const float*)d_in[4];

    float* context = (float*)d_out;                          // [B, H]
    float* weights = (float*)d_out + (size_t)B_DIM * H_DIM;  // [B, S]

    cudaFuncSetAttribute(scores_gemm_mma,
                         cudaFuncAttributeMaxDynamicSharedMemorySize, GEMM_SMEM);

    convert_w_kernel<<<NTILES * NKCH, 256>>>(W);

    scores_gemm_mma<<<dim3(NMTILES, NTILES), 512, GEMM_SMEM>>>(hidden, bias, v);

    softmax_kernel<<<B_DIM, 256>>>(mask, weights);

    context_part_kernel<<<dim3(SCHUNK, B_DIM), 128>>>(hidden, weights);
    context_reduce_kernel<<<(B_DIM * H_DIM) / 256, 256>>>(context);
}